// round 12
// baseline (speedup 1.0000x reference)
#include <cuda_runtime.h>

// DTW 65536 x 512 — 4 CTAs x 128 threads, 1 column/thread, R=32 rows/tick.
// R12 = R10 with the shfl+SEL handoff replaced by a uniform padded-smem
// exchange of PRODUCER-side pre-min'd boundary values:
//   pm[r] = min(ev[r-1], ev[r]),  pm[0] = min(prev_last, ev[0])
// which equals m[r] = min(diag, left) for the right neighbor. Consumer chain:
//   q = pm[r]-S; S = fma(ts,ts,S); cm = min(cm,q); ev[r] = S+cm.
// Thread tid reads exch[tid-1] (tid 0 reads the cross-CTA staging buffer),
// so lane and warp boundaries are handled identically: no SHFL, no per-value
// SEL, no separate edgebuf. g_edge / lbuf also carry pm.

#define N_ROWS  65536
#define NCTA    4
#define NTHR    128
#define NWARP   4
#define R       32
#define NTICK   (N_ROWS / R)          // 2048
#define NITER   (NTICK + NTHR - 1)    // 2175
#define CHUNK   32                    // ticks per cross-CTA chunk
#define XSTRIDE 36                    // floats per ring slot (32 data + 4 pad)
#define ESTRIDE 36                    // floats per exchange slot (32 + 4 pad)

__device__ __align__(16) float g_edge[NCTA - 1][N_ROWS];
__device__ int g_flag[NCTA - 1];

__global__ void dtw_init_flags()
{
    if (threadIdx.x < NCTA - 1) g_flag[threadIdx.x] = 0;
}

__device__ __forceinline__ int flag_acquire(const int* p)
{
    int v;
    asm volatile("ld.acquire.gpu.global.b32 %0, [%1];" : "=r"(v) : "l"(p) : "memory");
    return v;
}

__device__ __forceinline__ void flag_release(int* p, int v)
{
    asm volatile("st.release.gpu.global.b32 [%0], %1;" :: "l"(p), "r"(v) : "memory");
}

__global__ __launch_bounds__(NTHR, 1)
void dtw_exch_kernel(const float* __restrict__ x,
                     const float* __restrict__ kern,
                     float* __restrict__ out)
{
    __shared__ __align__(16) float s_xring[NWARP][64 * XSTRIDE]; // 36 KB x rings
    __shared__ __align__(16) float s_lbuf[2][CHUNK * R];         // 8 KB cross-CTA staging (pm)
    __shared__ __align__(16) float s_exch[2][NTHR][ESTRIDE];     // 36 KB pm exchange

    const int   c   = (int)blockIdx.x;
    const int   tid = (int)threadIdx.x;
    const int   w   = tid >> 5;
    const int   l   = tid & 31;
    const float INF = __int_as_float(0x7f800000);

    const float kv    = kern[c * NTHR + tid];
    const bool  pred0 = (c == 0) && (tid == 0);
    float* const myring = s_xring[w];

    // ---- initial x ring fill: ticks [-32w-31, -32w+32], 2 slots per lane ----
    #pragma unroll
    for (int k2 = 0; k2 < 2; ++k2) {
        const int T  = -32 * w - 31 + l + 32 * k2;
        const int Tc = min(max(T, 0), NTICK - 1);
        const float4* xp = (const float4*)(x + Tc * R);
        float4* dst = (float4*)&myring[(((unsigned)T) & 63u) * XSTRIDE];
        #pragma unroll
        for (int q = 0; q < 8; ++q) dst[q] = xp[q];
    }

    // ---- init exchange buffers to +INF (upper boundary / pre-start) ----
    #pragma unroll
    for (int k2 = 0; k2 < 2 * ESTRIDE; ++k2)
        s_exch[k2 >= ESTRIDE][tid][k2 >= ESTRIDE ? k2 - ESTRIDE : k2] = INF;

    // ---- prestage chunk 0 of the left-CTA boundary (pm values) ----
    if (c == 0) {
        #pragma unroll
        for (int k = 0; k < (2 * CHUNK * R) / NTHR; ++k)
            s_lbuf[0][tid + NTHR * k] = INF;
    } else {
        if (tid == 0) {
            while (flag_acquire(&g_flag[c - 1]) < CHUNK) { }
        }
        __syncthreads();
        #pragma unroll
        for (int k2 = 0; k2 < 2; ++k2)
            *(float4*)&s_lbuf[0][4 * (2 * tid + k2)] =
                __ldcg((const float4*)g_edge[c - 1] + 2 * tid + k2);
    }
    __syncthreads();

    float vprev = INF;        // own ev[31] of previous active tick
    float prev_last = INF;    // same, feeding pm[0] of next tick

    for (int i = 0; i < NITER; ++i) {
        // ---- every 32 iters: refill my ring + cross-CTA chunk staging ----
        if ((i & (CHUNK - 1)) == 0) {
            {
                const int T  = i - 32 * w + l;
                const int Tc = min(max(T, 0), NTICK - 1);
                const float4* xp = (const float4*)(x + Tc * R);
                float4* dst = (float4*)&myring[(((unsigned)T) & 63u) * XSTRIDE];
                #pragma unroll
                for (int q = 0; q < 8; ++q) dst[q] = xp[q];
            }
            if (c > 0) {
                const int base = i + CHUNK;
                if (base < NTICK) {
                    if (tid == 0) {
                        const int need = min(base + CHUNK, NTICK);
                        while (flag_acquire(&g_flag[c - 1]) < need) { }
                    }
                    __syncthreads();
                    const int buf = ((i >> 5) + 1) & 1;
                    #pragma unroll
                    for (int k2 = 0; k2 < 2; ++k2)
                        *(float4*)&s_lbuf[buf][4 * (2 * tid + k2)] =
                            __ldcg((const float4*)(g_edge[c - 1] + base * R) + 2 * tid + k2);
                    // consumed >= 32 iterations later; the per-iteration
                    // barrier below orders these STS before those reads.
                }
            }
        }

        // ---- m = pm from left neighbor: ONE address select, 8 LDS.128 ----
        float m[R];
        {
            const float* src = (tid == 0)
                ? &s_lbuf[(i >> 5) & 1][(i & (CHUNK - 1)) * R]
                : &s_exch[(i & 1) ^ 1][tid - 1][0];
            #pragma unroll
            for (int h = 0; h < 8; ++h) {
                const float4 a = ((const float4*)src)[h];
                m[4*h] = a.x; m[4*h+1] = a.y; m[4*h+2] = a.z; m[4*h+3] = a.w;
            }
        }
        // virtual 0 at (row 0, col -1): m[0] = min(INF, 0) = 0 at cell (0,0)
        m[0] = (pred0 && i == 0) ? 0.0f : m[0];

        const int  t      = i - tid;
        const bool active = (t >= 0) && (t < NTICK);

        // ---- x residuals (parallel, off-chain) ----
        float ts[R];
        {
            const float* sp = &myring[(((unsigned)t) & 63u) * XSTRIDE];
            #pragma unroll
            for (int h = 0; h < 8; ++h) {
                const float4 a = ((const float4*)sp)[h];
                ts[4*h]   = kv - a.x;
                ts[4*h+1] = kv - a.y;
                ts[4*h+2] = kv - a.z;
                ts[4*h+3] = kv - a.w;
            }
        }

        // ---- min-plus prefix: two concurrent 4-cyc chains ----
        float ev[R];
        float S  = ts[0] * ts[0];
        float cm = fminf(vprev, m[0]);
        ev[0] = S + cm;
        #pragma unroll
        for (int r = 1; r < R; ++r) {
            const float q = m[r] - S;           // m[r] - S[r-1]
            S  = fmaf(ts[r], ts[r], S);         // S[r]
            cm = fminf(cm, q);                  // cm[r]
            ev[r] = S + cm;
        }

        // ---- producer-side pre-min for the right neighbor ----
        float pm[R];
        pm[0] = fminf(prev_last, ev[0]);
        #pragma unroll
        for (int r = 1; r < R; ++r)
            pm[r] = fminf(ev[r - 1], ev[r]);

        vprev     = active ? ev[R - 1] : vprev;
        prev_last = active ? ev[R - 1] : prev_last;

        // ---- publish: exch for tid<127, global for tid 127 ----
        if (tid < NTHR - 1) {
            float4* dst = (float4*)&s_exch[i & 1][tid][0];
            #pragma unroll
            for (int q = 0; q < 8; ++q)
                dst[q] = make_float4(pm[4*q], pm[4*q+1], pm[4*q+2], pm[4*q+3]);
        } else if (active) {
            if (c < NCTA - 1) {
                float4* ep = (float4*)(g_edge[c] + t * R);
                #pragma unroll
                for (int q = 0; q < 8; ++q)
                    ep[q] = make_float4(pm[4*q], pm[4*q+1], pm[4*q+2], pm[4*q+3]);
                if ((t & 7) == 7)
                    flag_release(&g_flag[c], t + 1);
            } else {
                float4* op = (float4*)(out + t * R);
                #pragma unroll
                for (int q = 0; q < 8; ++q)
                    op[q] = make_float4(ev[4*q], ev[4*q+1], ev[4*q+2], ev[4*q+3]);
            }
        }

        __syncthreads();
    }
}

extern "C" void kernel_launch(void* const* d_in, const int* in_sizes, int n_in,
                              void* d_out, int out_size)
{
    const float* x = (const float*)d_in[0];   // input  [65536]
    const float* k = (const float*)d_in[1];   // kernel [512]
    float* out = (float*)d_out;               // [65536] float32

    dtw_init_flags<<<1, 32>>>();
    dtw_exch_kernel<<<NCTA, NTHR>>>(x, k, out);
}

// round 14
// speedup vs baseline: 1.2461x; 1.2461x over previous
#include <cuda_runtime.h>

// DTW 65536 x 512 — 4 CTAs x 128 threads, 1 column/thread, R=64 rows/tick.
// R14 = R13 (R=64, pm-via-shfl, dynamic smem) with the kernel_launch
// static-guard removed: cudaFuncSetAttribute is called unconditionally
// (capture-safe, deterministic) per the harness contract.
//   * R=64: iteration count 2175 -> 1151; the inherent 511-column wavefront
//     skew costs 511 of 1535 ideal iters instead of 511 of 2559
//   * producer-side pre-min pm[r]=min(ev[r-1],ev[r]) carried in registers,
//     handed off via shfl; consumer uses it directly as m=min(diag,left)
//   * dynamic shared memory: 64-deep per-warp x rings at R=64 (85.5 KB)

#define N_ROWS  65536
#define NCTA    4
#define NTHR    128
#define NWARP   4
#define R       64
#define NTICK   (N_ROWS / R)           // 1024
#define NITER   (NTICK + NTHR - 1)     // 1151
#define CHUNK   32                     // ticks per cross-CTA chunk
#define XSTRIDE 68                     // floats per ring slot (64 data + 4 pad)
#define RSLOTS  64

// dynamic smem layout (float offsets)
#define OFF_RING   0
#define OFF_LBUF   (NWARP * RSLOTS * XSTRIDE)            // 17408
#define OFF_EB     (OFF_LBUF + 2 * CHUNK * R)            // 21504
#define SMEM_FLOATS (OFF_EB + 2 * (NWARP - 1) * R)       // 21888
#define SMEM_BYTES (SMEM_FLOATS * 4)                     // 87552

__device__ __align__(16) float g_edge[NCTA - 1][N_ROWS];
__device__ int g_flag[NCTA - 1];

__global__ void dtw_init_flags()
{
    if (threadIdx.x < NCTA - 1) g_flag[threadIdx.x] = 0;
}

__device__ __forceinline__ int flag_acquire(const int* p)
{
    int v;
    asm volatile("ld.acquire.gpu.global.b32 %0, [%1];" : "=r"(v) : "l"(p) : "memory");
    return v;
}

__device__ __forceinline__ void flag_release(int* p, int v)
{
    asm volatile("st.release.gpu.global.b32 [%0], %1;" :: "l"(p), "r"(v) : "memory");
}

__global__ __launch_bounds__(NTHR, 1)
void dtw_r64_kernel(const float* __restrict__ x,
                    const float* __restrict__ kern,
                    float* __restrict__ out)
{
    extern __shared__ __align__(16) float smem[];
    float* const lbuf = smem + OFF_LBUF;   // [2][CHUNK*R] cross-CTA pm staging
    float* const eb   = smem + OFF_EB;     // [2][NWARP-1][R] warp-boundary pm

    const int   c   = (int)blockIdx.x;
    const int   tid = (int)threadIdx.x;
    const int   w   = tid >> 5;
    const int   l   = tid & 31;
    const float INF = __int_as_float(0x7f800000);

    const float kv    = kern[c * NTHR + tid];
    const bool  pred0 = (c == 0) && (tid == 0);
    float* const myring = smem + OFF_RING + w * (RSLOTS * XSTRIDE);

    // ---- initial x ring fill: ticks [-32w-31, -32w+32], 2 slots per lane ----
    #pragma unroll
    for (int k2 = 0; k2 < 2; ++k2) {
        const int T  = -32 * w - 31 + l + 32 * k2;
        const int Tc = min(max(T, 0), NTICK - 1);
        const float4* xp = (const float4*)(x + Tc * R);
        float4* dst = (float4*)&myring[(((unsigned)T) & 63u) * XSTRIDE];
        #pragma unroll
        for (int q = 0; q < 16; ++q) dst[q] = xp[q];
    }

    // ---- init warp-boundary buffers (hygiene: avoid NaN garbage) ----
    for (int k2 = tid; k2 < 2 * (NWARP - 1) * R; k2 += NTHR)
        eb[k2] = INF;

    // ---- prestage chunk 0 of the left-CTA boundary (pm values) ----
    if (c == 0) {
        #pragma unroll
        for (int k2 = 0; k2 < (2 * CHUNK * R) / NTHR; ++k2)
            lbuf[tid + NTHR * k2] = INF;          // both buffers: never restaged
    } else {
        if (tid == 0) {
            while (flag_acquire(&g_flag[c - 1]) < CHUNK) { }
        }
        __syncthreads();
        #pragma unroll
        for (int k2 = 0; k2 < 4; ++k2)
            *(float4*)&lbuf[16 * tid + 4 * k2] =
                __ldcg((const float4*)g_edge[c - 1] + 4 * tid + k2);
    }
    __syncthreads();

    float pm[R];
    #pragma unroll
    for (int r = 0; r < R; ++r) pm[r] = INF;
    float vlast = INF;                 // own previous active tick's ev[R-1]

    const bool wout = (c == NCTA - 1) && (tid == NTHR - 1);

    for (int i = 0; i < NITER; ++i) {
        // ---- m from left neighbor: shfl of neighbor's previous-tick pm ----
        float L[R];
        #pragma unroll
        for (int r = 0; r < R; ++r)
            L[r] = __shfl_up_sync(0xffffffffu, pm[r], 1);

        // ---- every 32 iters: refill my ring + cross-CTA chunk staging ----
        if ((i & (CHUNK - 1)) == 0) {
            {
                const int T  = i - 32 * w + l;
                const int Tc = min(max(T, 0), NTICK - 1);
                const float4* xp = (const float4*)(x + Tc * R);
                float4* dst = (float4*)&myring[(((unsigned)T) & 63u) * XSTRIDE];
                #pragma unroll
                for (int q = 0; q < 16; ++q) dst[q] = xp[q];
            }
            if (c > 0) {
                const int base = i + CHUNK;
                if (base < NTICK) {
                    if (tid == 0) {
                        const int need = min(base + CHUNK, NTICK);
                        while (flag_acquire(&g_flag[c - 1]) < need) { }
                    }
                    __syncthreads();
                    const int buf = ((i >> 5) + 1) & 1;
                    #pragma unroll
                    for (int k2 = 0; k2 < 4; ++k2)
                        *(float4*)&lbuf[buf * (CHUNK * R) + 16 * tid + 4 * k2] =
                            __ldcg((const float4*)(g_edge[c - 1] + base * R) + 4 * tid + k2);
                    // consumed >= 32 iterations later; per-iteration barrier
                    // below orders these STS before those reads.
                }
            }
        }

        // ---- lane-0 boundary source (warp-uniform branch, broadcast LDS) ----
        {
            const float* src = (w == 0)
                ? &lbuf[((i >> 5) & 1) * (CHUNK * R) + (i & (CHUNK - 1)) * R]
                : &eb[((i & 1) ^ 1) * ((NWARP - 1) * R) + (w - 1) * R];
            #pragma unroll
            for (int h = 0; h < 16; ++h) {
                const float4 a = ((const float4*)src)[h];
                L[4*h]   = (l == 0) ? a.x : L[4*h];
                L[4*h+1] = (l == 0) ? a.y : L[4*h+1];
                L[4*h+2] = (l == 0) ? a.z : L[4*h+2];
                L[4*h+3] = (l == 0) ? a.w : L[4*h+3];
            }
        }
        // virtual 0 at (row 0, col -1): left-use only, at cell (0,0)
        L[0] = (pred0 && i == 0) ? 0.0f : L[0];

        const int  t      = i - tid;
        const bool active = (t >= 0) && (t < NTICK);
        const bool do_out = wout && active;

        // ---- chain: min-plus prefix + producer-side pre-min, ev rolling ----
        const float4* sp4 = (const float4*)&myring[(((unsigned)t) & 63u) * XSTRIDE];
        float S, cm, ep;
        float4 v4;
        {
            const float4 xa = sp4[0];
            const float tt = kv - xa.x;
            S  = tt * tt;
            cm = fminf(vlast, L[0]);
            ep = S + cm;                 // ev[0]
            pm[0] = fminf(vlast, ep);
            v4.x = ep;
            #pragma unroll
            for (int r = 1; r < 4; ++r) {
                const float t2 = kv - ((const float*)&xa)[r];
                const float q  = L[r] - S;
                S  = fmaf(t2, t2, S);
                cm = fminf(cm, q);
                const float e = S + cm;
                pm[r] = fminf(ep, e);
                ((float*)&v4)[r] = e;
                ep = e;
            }
            if (do_out) ((float4*)(out + t * R))[0] = v4;
        }
        #pragma unroll
        for (int h = 1; h < 16; ++h) {
            const float4 xa = sp4[h];
            #pragma unroll
            for (int r = 0; r < 4; ++r) {
                const float t2 = kv - ((const float*)&xa)[r];
                const float q  = L[4*h + r] - S;
                S  = fmaf(t2, t2, S);
                cm = fminf(cm, q);
                const float e = S + cm;
                pm[4*h + r] = fminf(ep, e);
                ((float*)&v4)[r] = e;
                ep = e;
            }
            if (do_out) ((float4*)(out + t * R))[h] = v4;
        }
        vlast = active ? ep : vlast;

        // ---- publish pm: warp boundary via smem, CTA boundary via global ----
        if (l == 31) {
            if (w < NWARP - 1) {
                float4* d = (float4*)&eb[(i & 1) * ((NWARP - 1) * R) + w * R];
                #pragma unroll
                for (int q = 0; q < 16; ++q)
                    d[q] = make_float4(pm[4*q], pm[4*q+1], pm[4*q+2], pm[4*q+3]);
            } else if (active && c < NCTA - 1) {
                float4* ep4 = (float4*)(g_edge[c] + t * R);
                #pragma unroll
                for (int q = 0; q < 16; ++q)
                    ep4[q] = make_float4(pm[4*q], pm[4*q+1], pm[4*q+2], pm[4*q+3]);
                if ((t & 3) == 3)
                    flag_release(&g_flag[c], t + 1);
            }
        }

        __syncthreads();
    }
}

extern "C" void kernel_launch(void* const* d_in, const int* in_sizes, int n_in,
                              void* d_out, int out_size)
{
    const float* x = (const float*)d_in[0];   // input  [65536]
    const float* k = (const float*)d_in[1];   // kernel [512]
    float* out = (float*)d_out;               // [65536] float32

    // Unconditional on every call (no static guards): cudaFuncSetAttribute is
    // not a stream operation and is capture-safe; same work every invocation.
    cudaFuncSetAttribute(dtw_r64_kernel,
                         cudaFuncAttributeMaxDynamicSharedMemorySize,
                         SMEM_BYTES);

    dtw_init_flags<<<1, 32>>>();
    dtw_r64_kernel<<<NCTA, NTHR, SMEM_BYTES>>>(x, k, out);
}